// round 4
// baseline (speedup 1.0000x reference)
#include <cuda_runtime.h>
#include <cstdint>

#define HID 768
#define TSEQ 1024
#define BATCH 64
#define NCTA 128

// xp scratch: [d][t][b][3072]  (1.61 GB)
__device__ float g_xp[402653184];
// h double buffer: [buf][d][b][HID], values tf32-rounded
__device__ float g_h[2 * 2 * BATCH * HID];
// final states: [d][{h,c}][b][HID] -> hf, cf, hb, cb
__device__ float g_hc[4 * BATCH * HID];
// grid barrier
__device__ unsigned g_cnt;
__device__ unsigned g_gen;

__global__ void init_kernel() { g_cnt = 0; g_gen = 0; }

// ---------- helpers ----------
__device__ __forceinline__ unsigned f2tf(float f) {
    unsigned u;
    asm("cvt.rna.tf32.f32 %0, %1;" : "=r"(u) : "f"(f));
    return u;
}
__device__ __forceinline__ void cp16(float* sdst, const float* gsrc) {
    unsigned sa = (unsigned)__cvta_generic_to_shared(sdst);
    asm volatile("cp.async.cg.shared.global [%0], [%1], 16;" :: "r"(sa), "l"(gsrc));
}
__device__ __forceinline__ void cp_commit() { asm volatile("cp.async.commit_group;"); }
template <int N> __device__ __forceinline__ void cp_wait() {
    asm volatile("cp.async.wait_group %0;" :: "n"(N));
}
__device__ __forceinline__ void mma_tf32(float* acc, const unsigned* a, unsigned b0, unsigned b1) {
    asm volatile(
        "mma.sync.aligned.m16n8k8.row.col.f32.tf32.tf32.f32 "
        "{%0,%1,%2,%3},{%4,%5,%6,%7},{%8,%9},{%0,%1,%2,%3};"
        : "+f"(acc[0]), "+f"(acc[1]), "+f"(acc[2]), "+f"(acc[3])
        : "r"(a[0]), "r"(a[1]), "r"(a[2]), "r"(a[3]), "r"(b0), "r"(b1));
}
__device__ __forceinline__ float sigm(float x) {
    return __fdividef(1.0f, 1.0f + __expf(-x));
}
__device__ __forceinline__ float tanh2(float x) {
    return 2.0f * sigm(2.0f * x) - 1.0f;
}
__device__ __forceinline__ void gsync(unsigned target) {
    __threadfence();
    __syncthreads();
    if (threadIdx.x == 0) {
        unsigned a = atomicAdd(&g_cnt, 1u);
        if (a == NCTA - 1) {
            g_cnt = 0;
            __threadfence();
            atomicAdd(&g_gen, 1u);
        } else {
            unsigned v;
            do {
                asm volatile("ld.acquire.gpu.u32 %0, [%1];" : "=r"(v) : "l"(&g_gen));
            } while (v < target);
        }
    }
    __syncthreads();
}

// ================= Phase A: xp = x @ [Wxf;Wxb]^T + bias, scattered =================
// M=65536, N=6144, K=512. CTA tile 128x64, BK=32, 256 threads (8 warps, 4x2 of 32x32).
__global__ __launch_bounds__(256, 2) void xproj_kernel(
    const float* __restrict__ X, const float* __restrict__ Wxf,
    const float* __restrict__ Wxb, const float* __restrict__ bf,
    const float* __restrict__ bb)
{
    extern __shared__ float sm[];
    float* As = sm;                  // 2 x 128 x 36
    float* Bs = sm + 2 * 128 * 36;   // 2 x 64 x 36
    const int tid = threadIdx.x;
    const int bn = blockIdx.x, bm = blockIdx.y;
    const int warp = tid >> 5, lane = tid & 31;
    const int wm = warp >> 1, wn = warp & 1;
    const int gq = lane >> 2, tig = lane & 3;

    auto stage = [&](int buf, int k0) {
        float* Ad = As + buf * (128 * 36);
        float* Bd = Bs + buf * (64 * 36);
#pragma unroll
        for (int j = 0; j < 4; ++j) {
            int idx = j * 256 + tid;
            int r = idx >> 3, q = idx & 7;
            cp16(Ad + r * 36 + q * 4, X + (size_t)(bm * 128 + r) * 512 + k0 + q * 4);
        }
#pragma unroll
        for (int j = 0; j < 2; ++j) {
            int idx = j * 256 + tid;
            int r = idx >> 3, q = idx & 7;
            int n = bn * 64 + r;
            const float* src = (n < 3072) ? (Wxf + (size_t)n * 512 + k0 + q * 4)
                                          : (Wxb + (size_t)(n - 3072) * 512 + k0 + q * 4);
            cp16(Bd + r * 36 + q * 4, src);
        }
        cp_commit();
    };

    float acc[2][4][4];
#pragma unroll
    for (int a = 0; a < 2; ++a)
#pragma unroll
        for (int b = 0; b < 4; ++b)
#pragma unroll
            for (int c = 0; c < 4; ++c) acc[a][b][c] = 0.f;

    stage(0, 0);
#pragma unroll 1
    for (int it = 0; it < 16; ++it) {
        if (it < 15) { stage((it + 1) & 1, (it + 1) * 32); cp_wait<1>(); }
        else { cp_wait<0>(); }
        __syncthreads();
        const float* Ab = As + (it & 1) * (128 * 36);
        const float* Bb = Bs + (it & 1) * (64 * 36);
#pragma unroll
        for (int k8 = 0; k8 < 4; ++k8) {
            unsigned af[2][4];
#pragma unroll
            for (int mt = 0; mt < 2; ++mt) {
                const float* ap = Ab + (wm * 32 + mt * 16 + gq) * 36 + k8 * 8 + tig;
                af[mt][0] = f2tf(ap[0]);
                af[mt][1] = f2tf(ap[8 * 36]);
                af[mt][2] = f2tf(ap[4]);
                af[mt][3] = f2tf(ap[8 * 36 + 4]);
            }
#pragma unroll
            for (int nt = 0; nt < 4; ++nt) {
                const float* bp = Bb + (wn * 32 + nt * 8 + gq) * 36 + k8 * 8 + tig;
                unsigned b0 = f2tf(bp[0]);
                unsigned b1 = f2tf(bp[4]);
                mma_tf32(acc[0][nt], af[0], b0, b1);
                mma_tf32(acc[1][nt], af[1], b0, b1);
            }
        }
        __syncthreads();
    }
    // epilogue: bias + time-reversal scatter into g_xp[d][t][b][3072]
#pragma unroll
    for (int mt = 0; mt < 2; ++mt) {
#pragma unroll
        for (int r = 0; r < 2; ++r) {
            int m = bm * 128 + wm * 32 + mt * 16 + gq + r * 8;
            int b = m >> 10;
            int tx = m & 1023;
#pragma unroll
            for (int nt = 0; nt < 4; ++nt) {
                int n0 = bn * 64 + wn * 32 + nt * 8 + tig * 2;
                int d = (n0 >= 3072) ? 1 : 0;
                int g = n0 - d * 3072;
                int t = d ? (1023 - tx) : tx;
                float2 v;
                v.x = acc[mt][nt][r * 2 + 0] + (d ? bb[g] : bf[g]);
                v.y = acc[mt][nt][r * 2 + 1] + (d ? bb[g + 1] : bf[g + 1]);
                size_t addr = ((size_t)(d * 1024 + t) * 64 + b) * 3072 + g;
                *(float2*)(g_xp + addr) = v;
            }
        }
    }
}

// ================= Phase B: persistent bidirectional recurrence =================
// 128 CTAs x 128 threads. CTA: dir = cid>>6, unit slice us = cid&63 (12 units).
// smem: Wh_s[48][772] tf32 (resident), A_s 2 x [64][132] h-panels, z_s[64][52].
__global__ __launch_bounds__(128, 1) void recur_kernel(
    const float* __restrict__ Whf, const float* __restrict__ Whb)
{
    extern __shared__ float sm[];
    float* Wh_s = sm;                          // 48*772
    float* A_s  = sm + 48 * 772;               // 2 * 64*132 = 16896
    float* z_s  = sm + 48 * 772 + 16896;       // 64*52

    const int tid = threadIdx.x;
    const int warp = tid >> 5, lane = tid & 31;
    const int gq = lane >> 2, tig = lane & 3;
    const int ng = warp >> 1;   // n-half: gate cols [ng*24, ng*24+24)
    const int kp = warp & 1;    // k8 parity
    const int cid = blockIdx.x;
    const int d = cid >> 6, us = cid & 63;
    const float* Wh = d ? Whb : Whf;

    // load + tf32-convert resident weight slice (rows: f,i,g,o x 12 units)
    for (int v = tid; v < 48 * 192; v += 128) {
        int r = v / 192, q = v % 192;
        int gb = r / 12, uu = r % 12;
        float4 w = *(const float4*)(Wh + (size_t)(gb * 768 + us * 12 + uu) * 768 + q * 4);
        float4 o;
        o.x = __uint_as_float(f2tf(w.x));
        o.y = __uint_as_float(f2tf(w.y));
        o.z = __uint_as_float(f2tf(w.z));
        o.w = __uint_as_float(f2tf(w.w));
        *(float4*)(Wh_s + r * 772 + q * 4) = o;
    }
    // zero h buf0 for my slice
    for (int v = tid; v < 768; v += 128) {
        int b = v / 12, uu = v % 12;
        g_h[((size_t)(0 * 2 + d) * 64 + b) * 768 + us * 12 + uu] = 0.f;
    }
    float cc[6];
#pragma unroll
    for (int j = 0; j < 6; ++j) cc[j] = 0.f;

    gsync(1);

#pragma unroll 1
    for (int t = 0; t < 1024; ++t) {
        const float* hcur = g_h + (size_t)((t & 1) * 2 + d) * BATCH * HID;
        const float* xpt = g_xp + (size_t)(d * 1024 + t) * BATCH * 3072;

        auto stage_panel = [&](int p, float* dst) {
            const float* src = hcur + p * 128;
#pragma unroll
            for (int j = 0; j < 16; ++j) {
                int idx = j * 128 + tid;
                int b = idx >> 5, q = idx & 31;
                cp16(dst + b * 132 + q * 4, src + (size_t)b * 768 + q * 4);
            }
        };

        // stage xp gather (into z_s) + panel 0, then panel 1
#pragma unroll
        for (int j = 0; j < 6; ++j) {
            int idx = j * 128 + tid;
            int b = idx / 12, seg = idx % 12;
            int blk = seg / 3, q = seg % 3;
            cp16(z_s + b * 52 + blk * 12 + q * 4,
                 xpt + (size_t)b * 3072 + blk * 768 + us * 12 + q * 4);
        }
        stage_panel(0, A_s);
        cp_commit();
        stage_panel(1, A_s + 8448);
        cp_commit();

        float acc[4][3][4];
#pragma unroll
        for (int a = 0; a < 4; ++a)
#pragma unroll
            for (int b = 0; b < 3; ++b)
#pragma unroll
                for (int c = 0; c < 4; ++c) acc[a][b][c] = 0.f;

#pragma unroll 1
        for (int p = 0; p < 6; ++p) {
            if (p < 5) { cp_wait<1>(); } else { cp_wait<0>(); }
            __syncthreads();
            const float* Ab = A_s + (p & 1) * 8448;
#pragma unroll
            for (int k8h = 0; k8h < 8; ++k8h) {
                int k8 = k8h * 2 + kp;
                int kk = k8 * 8;
                int kg = p * 128 + kk;
                unsigned af[4][4];
#pragma unroll
                for (int mt = 0; mt < 4; ++mt) {
                    const float* ap = Ab + (mt * 16 + gq) * 132 + kk + tig;
                    af[mt][0] = __float_as_uint(ap[0]);
                    af[mt][1] = __float_as_uint(ap[8 * 132]);
                    af[mt][2] = __float_as_uint(ap[4]);
                    af[mt][3] = __float_as_uint(ap[8 * 132 + 4]);
                }
#pragma unroll
                for (int nt = 0; nt < 3; ++nt) {
                    const float* bp = Wh_s + (ng * 24 + nt * 8 + gq) * 772 + kg + tig;
                    unsigned b0 = __float_as_uint(bp[0]);
                    unsigned b1 = __float_as_uint(bp[4]);
#pragma unroll
                    for (int mt = 0; mt < 4; ++mt)
                        mma_tf32(acc[mt][nt], af[mt], b0, b1);
                }
            }
            __syncthreads();
            if (p < 4) { stage_panel(p + 2, A_s + (p & 1) * 8448); cp_commit(); }
        }

        // reduce k-parities into z_s (which holds xp)
        if (kp == 0) {
#pragma unroll
            for (int mt = 0; mt < 4; ++mt)
#pragma unroll
                for (int nt = 0; nt < 3; ++nt) {
                    int row = mt * 16 + gq;
                    int col = ng * 24 + nt * 8 + 2 * tig;
                    float2* z0 = (float2*)(z_s + row * 52 + col);
                    float2* z1 = (float2*)(z_s + (row + 8) * 52 + col);
                    float2 a = *z0;
                    a.x += acc[mt][nt][0]; a.y += acc[mt][nt][1];
                    *z0 = a;
                    float2 b2 = *z1;
                    b2.x += acc[mt][nt][2]; b2.y += acc[mt][nt][3];
                    *z1 = b2;
                }
        }
        __syncthreads();
        if (kp == 1) {
#pragma unroll
            for (int mt = 0; mt < 4; ++mt)
#pragma unroll
                for (int nt = 0; nt < 3; ++nt) {
                    int row = mt * 16 + gq;
                    int col = ng * 24 + nt * 8 + 2 * tig;
                    float2* z0 = (float2*)(z_s + row * 52 + col);
                    float2* z1 = (float2*)(z_s + (row + 8) * 52 + col);
                    float2 a = *z0;
                    a.x += acc[mt][nt][0]; a.y += acc[mt][nt][1];
                    *z0 = a;
                    float2 b2 = *z1;
                    b2.x += acc[mt][nt][2]; b2.y += acc[mt][nt][3];
                    *z1 = b2;
                }
        }
        __syncthreads();

        // pointwise gates + state update
        int nb = (t + 1) & 1;
#pragma unroll
        for (int j = 0; j < 6; ++j) {
            int idx = j * 128 + tid;
            int b = idx / 12, uu = idx % 12;
            const float* zr = z_s + b * 52;
            float f = sigm(zr[uu]);
            float i = sigm(zr[12 + uu]);
            float g = tanh2(zr[24 + uu]);
            float o = sigm(zr[36 + uu]);
            float c = f * cc[j] + i * g;
            cc[j] = c;
            float h = o * tanh2(c);
            g_h[((size_t)(nb * 2 + d) * 64 + b) * 768 + us * 12 + uu] =
                __uint_as_float(f2tf(h));
            if (t == 1023) {
                int unit = us * 12 + uu;
                g_hc[((size_t)(d * 2 + 0) * 64 + b) * 768 + unit] = h;
                g_hc[((size_t)(d * 2 + 1) * 64 + b) * 768 + unit] = c;
            }
        }
        gsync((unsigned)(t + 2));
    }
}

// ================= Phase C: out = [hf|hb] @ Why^T + by =================
__global__ __launch_bounds__(256) void outproj_kernel(
    const float* __restrict__ Why, const float* __restrict__ by,
    float* __restrict__ out)
{
    int w = blockIdx.x * 8 + (threadIdx.x >> 5);
    int lane = threadIdx.x & 31;
    int b = w >> 9, o = w & 511;
    const float* hf = g_hc + (size_t)b * 768;
    const float* hb = g_hc + 98304 + (size_t)b * 768;
    const float* wr = Why + (size_t)o * 1536;
    float s = 0.f;
    for (int k = lane; k < 768; k += 32) s += hf[k] * wr[k];
    for (int k = lane; k < 768; k += 32) s += hb[k] * wr[768 + k];
#pragma unroll
    for (int off = 16; off; off >>= 1) s += __shfl_xor_sync(0xffffffffu, s, off);
    if (lane == 0) out[(size_t)b * 512 + o] = s + by[o];
}

// ================= launch =================
extern "C" void kernel_launch(void* const* d_in, const int* in_sizes, int n_in,
                              void* d_out, int out_size) {
    const float* X   = (const float*)d_in[0];
    const float* Wxf = (const float*)d_in[1];
    const float* Whf = (const float*)d_in[2];
    const float* bf  = (const float*)d_in[3];
    const float* Wxb = (const float*)d_in[4];
    const float* Whb = (const float*)d_in[5];
    const float* bb  = (const float*)d_in[6];
    const float* Why = (const float*)d_in[7];
    const float* by  = (const float*)d_in[8];
    float* out = (float*)d_out;

    cudaFuncSetAttribute(xproj_kernel, cudaFuncAttributeMaxDynamicSharedMemorySize, 55296);
    cudaFuncSetAttribute(recur_kernel, cudaFuncAttributeMaxDynamicSharedMemorySize, 229120);

    init_kernel<<<1, 1>>>();
    xproj_kernel<<<dim3(96, 512), 256, 55296>>>(X, Wxf, Wxb, bf, bb);
    recur_kernel<<<NCTA, 128, 229120>>>(Whf, Whb);
    outproj_kernel<<<4096, 256>>>(Why, by, out);

    // write final states (h_fwd, c_fwd, h_bwd, c_bwd) if the output buffer holds them
    if (out_size >= 229376) {
        void* hc = nullptr;
        cudaGetSymbolAddress(&hc, g_hc);
        cudaMemcpyAsync(out + 32768, hc, 4 * 64 * 768 * sizeof(float),
                        cudaMemcpyDeviceToDevice, 0);
    }
}

// round 5
// speedup vs baseline: 1.3723x; 1.3723x over previous
#include <cuda_runtime.h>
#include <cuda_fp16.h>
#include <cstdint>

#define HID 768
#define TSEQ 1024
#define BATCH 64
#define NCTA 128

// ---------------- device scratch ----------------
// xp scratch: [d][t][b][3072] fp32 (1.61 GB)
__device__ float g_xp[402653184];
// fp16 copies of X and [Wxf;Wxb]
__device__ __half g_x16[64 * 1024 * 512];
__device__ __half g_wx16[6144 * 512];
// h double buffer fp16: [buf][d][b][HID]
__device__ __half g_h16[2 * 2 * BATCH * HID];
// final states fp32: [d][{h,c}][b][HID]
__device__ float g_hc[4 * BATCH * HID];
// grid barrier
__device__ unsigned g_cnt;
__device__ unsigned g_gen;

__global__ void init_kernel() { g_cnt = 0; g_gen = 0; }

// ---------------- helpers ----------------
__device__ __forceinline__ void cp16(void* sdst, const void* gsrc) {
    unsigned sa = (unsigned)__cvta_generic_to_shared(sdst);
    asm volatile("cp.async.cg.shared.global [%0], [%1], 16;" :: "r"(sa), "l"(gsrc));
}
__device__ __forceinline__ void cp_commit() { asm volatile("cp.async.commit_group;"); }
template <int N> __device__ __forceinline__ void cp_wait() {
    asm volatile("cp.async.wait_group %0;" :: "n"(N));
}
__device__ __forceinline__ void ldsm4(unsigned& r0, unsigned& r1, unsigned& r2,
                                      unsigned& r3, const void* p) {
    unsigned a = (unsigned)__cvta_generic_to_shared(p);
    asm volatile("ldmatrix.sync.aligned.m8n8.x4.shared.b16 {%0,%1,%2,%3}, [%4];"
                 : "=r"(r0), "=r"(r1), "=r"(r2), "=r"(r3) : "r"(a));
}
__device__ __forceinline__ void mma16(float* acc, unsigned a0, unsigned a1,
                                      unsigned a2, unsigned a3, unsigned b0, unsigned b1) {
    asm volatile(
        "mma.sync.aligned.m16n8k16.row.col.f32.f16.f16.f32 "
        "{%0,%1,%2,%3},{%4,%5,%6,%7},{%8,%9},{%0,%1,%2,%3};"
        : "+f"(acc[0]), "+f"(acc[1]), "+f"(acc[2]), "+f"(acc[3])
        : "r"(a0), "r"(a1), "r"(a2), "r"(a3), "r"(b0), "r"(b1));
}
__device__ __forceinline__ float sigm(float x) {
    return __fdividef(1.0f, 1.0f + __expf(-x));
}
__device__ __forceinline__ float tanh2(float x) {
    return 2.0f * sigm(2.0f * x) - 1.0f;
}
__device__ __forceinline__ void gsync(unsigned target) {
    __threadfence();
    __syncthreads();
    if (threadIdx.x == 0) {
        unsigned a = atomicAdd(&g_cnt, 1u);
        if (a == NCTA - 1) {
            g_cnt = 0;
            __threadfence();
            atomicAdd(&g_gen, 1u);
        } else {
            unsigned v;
            do {
                asm volatile("ld.acquire.gpu.u32 %0, [%1];" : "=r"(v) : "l"(&g_gen));
            } while (v < target);
        }
    }
    __syncthreads();
}

// ---------------- fp32 -> fp16 conversion ----------------
__global__ void conv_kernel(const float4* __restrict__ s, __half2* __restrict__ d, int n4) {
    int i = blockIdx.x * blockDim.x + threadIdx.x;
    if (i < n4) {
        float4 v = s[i];
        d[2 * i + 0] = __floats2half2_rn(v.x, v.y);
        d[2 * i + 1] = __floats2half2_rn(v.z, v.w);
    }
}

// ================= Phase A: xp = x @ [Wxf;Wxb]^T + bias (fp16 MMA) =================
// M=65536, N=6144, K=512. CTA 128x64, BK=32, 256 thr (8 warps 4x2, warp 32x32).
__global__ __launch_bounds__(256, 2) void xproj_kernel(
    const float* __restrict__ bf, const float* __restrict__ bb)
{
    extern __shared__ __half sm16[];
    __half* As = sm16;                   // 2 x 128 x 40
    __half* Bs = sm16 + 2 * 128 * 40;    // 2 x 64 x 40
    const int tid = threadIdx.x;
    const int bn = blockIdx.x, bm = blockIdx.y;
    const int warp = tid >> 5, lane = tid & 31;
    const int wm = warp >> 1, wn = warp & 1;
    const int gq = lane >> 2, tig = lane & 3;
    const int lrow = lane & 15, lcol = (lane >> 4) << 3;

    auto stage = [&](int buf, int k0) {
        __half* Ad = As + buf * (128 * 40);
        __half* Bd = Bs + buf * (64 * 40);
#pragma unroll
        for (int j = 0; j < 2; ++j) {
            int idx = j * 256 + tid;
            int r = idx >> 2, q = idx & 3;
            cp16(Ad + r * 40 + q * 8, g_x16 + (size_t)(bm * 128 + r) * 512 + k0 + q * 8);
        }
        {
            int r = tid >> 2, q = tid & 3;
            cp16(Bd + r * 40 + q * 8, g_wx16 + (size_t)(bn * 64 + r) * 512 + k0 + q * 8);
        }
        cp_commit();
    };

    float acc[2][4][4];
#pragma unroll
    for (int a = 0; a < 2; ++a)
#pragma unroll
        for (int b = 0; b < 4; ++b)
#pragma unroll
            for (int c = 0; c < 4; ++c) acc[a][b][c] = 0.f;

    stage(0, 0);
#pragma unroll 1
    for (int it = 0; it < 16; ++it) {
        if (it < 15) { stage((it + 1) & 1, (it + 1) * 32); cp_wait<1>(); }
        else { cp_wait<0>(); }
        __syncthreads();
        const __half* Ab = As + (it & 1) * (128 * 40);
        const __half* Bb = Bs + (it & 1) * (64 * 40);
#pragma unroll
        for (int k16 = 0; k16 < 2; ++k16) {
            int k0 = k16 * 16;
            unsigned a[2][4];
#pragma unroll
            for (int mt = 0; mt < 2; ++mt)
                ldsm4(a[mt][0], a[mt][1], a[mt][2], a[mt][3],
                      Ab + (wm * 32 + mt * 16 + lrow) * 40 + k0 + lcol);
#pragma unroll
            for (int np = 0; np < 2; ++np) {
                unsigned r0, r1, r2, r3;
                ldsm4(r0, r1, r2, r3,
                      Bb + (wn * 32 + np * 16 + lrow) * 40 + k0 + lcol);
                mma16(acc[0][np * 2 + 0], a[0][0], a[0][1], a[0][2], a[0][3], r0, r2);
                mma16(acc[0][np * 2 + 1], a[0][0], a[0][1], a[0][2], a[0][3], r1, r3);
                mma16(acc[1][np * 2 + 0], a[1][0], a[1][1], a[1][2], a[1][3], r0, r2);
                mma16(acc[1][np * 2 + 1], a[1][0], a[1][1], a[1][2], a[1][3], r1, r3);
            }
        }
        __syncthreads();
    }
    // epilogue: bias + time-reversal scatter into g_xp[d][t][b][3072] (fp32)
#pragma unroll
    for (int mt = 0; mt < 2; ++mt) {
#pragma unroll
        for (int r = 0; r < 2; ++r) {
            int m = bm * 128 + wm * 32 + mt * 16 + gq + r * 8;
            int b = m >> 10;
            int tx = m & 1023;
#pragma unroll
            for (int nt = 0; nt < 4; ++nt) {
                int n0 = bn * 64 + wn * 32 + nt * 8 + tig * 2;
                int d = (n0 >= 3072) ? 1 : 0;
                int g = n0 - d * 3072;
                int t = d ? (1023 - tx) : tx;
                float2 v;
                v.x = acc[mt][nt][r * 2 + 0] + (d ? bb[g] : bf[g]);
                v.y = acc[mt][nt][r * 2 + 1] + (d ? bb[g + 1] : bf[g + 1]);
                size_t addr = ((size_t)(d * 1024 + t) * 64 + b) * 3072 + g;
                *(float2*)(g_xp + addr) = v;
            }
        }
    }
}

// ================= Phase B: persistent bidirectional recurrence (fp16 MMA) =========
// 128 CTAs x 128 thr. CTA: dir d = cid>>6, unit slice us = cid&63 (12 units, 48 gate rows).
// Warps: (ng = warp>>1) n-half (24 gate cols), (kp = warp&1) contiguous k-half (384).
// smem: Wf[48 k16][6 nt][32 lanes] uint2 frags (73.7KB), A_s 64x776 half (99.3KB),
//       z_s 64x52 f32 (13.3KB). Total 186368 B, 1 CTA/SM.
__global__ __launch_bounds__(128, 1) void recur_kernel(
    const float* __restrict__ Whf, const float* __restrict__ Whb)
{
    extern __shared__ char smraw[];
    __half2* Wf2 = (__half2*)smraw;                        // 9216 uint2 = 73728 B
    __half* A_s  = (__half*)(smraw + 73728);               // 64 x 776
    float*  z_s  = (float*)(smraw + 73728 + 99328);        // 64 x 52

    const int tid = threadIdx.x;
    const int warp = tid >> 5, lane = tid & 31;
    const int gq = lane >> 2, tig = lane & 3;
    const int lrow = lane & 15, lcol = (lane >> 4) << 3;
    const int ng = warp >> 1;
    const int kp = warp & 1;
    const int g64 = ng * 32 + lane;     // 0..63 within kp group
    const int cid = blockIdx.x;
    const int d = cid >> 6, us = cid & 63;
    const float* Wh = d ? Whb : Whf;

    // --- pre-arrange resident weight fragments (once) ---
    for (int idx = tid; idx < 9216; idx += 128) {
        int c = idx / 192;            // k16 chunk 0..47
        int r = idx % 192;
        int nt = r >> 5;              // 0..5
        int ln = r & 31;
        int fq = ln >> 2, ft = ln & 3;
        int gr = nt * 8 + fq;         // gate row 0..47
        int gb = gr / 12, uu = gr % 12;
        const float* w = Wh + (size_t)(gb * 768 + us * 12 + uu) * 768 + c * 16 + ft * 2;
        Wf2[idx * 2 + 0] = __floats2half2_rn(w[0], w[1]);
        Wf2[idx * 2 + 1] = __floats2half2_rn(w[8], w[9]);
    }
    // zero h buf0 for my slice
    for (int v = tid; v < 768; v += 128) {
        int b = v / 12, uu = v % 12;
        g_h16[((size_t)(0 * 2 + d) * 64 + b) * 768 + us * 12 + uu] = __float2half(0.f);
    }
    float cc[6];
#pragma unroll
    for (int j = 0; j < 6; ++j) cc[j] = 0.f;

    gsync(1);

#pragma unroll 1
    for (int t = 0; t < 1024; ++t) {
        const __half* hcur = g_h16 + (size_t)((t & 1) * 2 + d) * BATCH * HID;
        const float* xpt = g_xp + (size_t)(d * 1024 + t) * BATCH * 3072;

        // --- stage: kp group stages its own k-half of h; kp=1 also stages xp into z_s ---
        if (kp == 0) {
#pragma unroll 4
            for (int j = 0; j < 48; ++j) {
                int idx = j * 64 + g64;
                int b = idx / 48, q = idx % 48;
                cp16(A_s + b * 776 + q * 8, hcur + (size_t)b * 768 + q * 8);
            }
            cp_commit();
            cp_wait<0>();
            asm volatile("bar.sync 1, 64;");
        } else {
#pragma unroll 4
            for (int j = 0; j < 48; ++j) {
                int idx = j * 64 + g64;
                int b = idx / 48, q = idx % 48;
                cp16(A_s + b * 776 + 384 + q * 8, hcur + (size_t)b * 768 + 384 + q * 8);
            }
            cp_commit();
#pragma unroll
            for (int j = 0; j < 12; ++j) {
                int idx = j * 64 + g64;
                int b = idx / 12, seg = idx % 12;
                int gate = seg / 3, q = seg % 3;
                cp16(z_s + b * 52 + gate * 12 + q * 4,
                     xpt + (size_t)b * 3072 + gate * 768 + us * 12 + q * 4);
            }
            cp_commit();
            cp_wait<1>();
            asm volatile("bar.sync 2, 64;");
        }

        // --- mainloop: 24 contiguous k16 chunks for this warp's k-half ---
        float acc[4][3][4];
#pragma unroll
        for (int a = 0; a < 4; ++a)
#pragma unroll
            for (int b = 0; b < 3; ++b)
#pragma unroll
                for (int c = 0; c < 4; ++c) acc[a][b][c] = 0.f;

        const uint2* Wfu = (const uint2*)Wf2;
#pragma unroll 2
        for (int ccnk = 0; ccnk < 24; ++ccnk) {
            int c = kp * 24 + ccnk;
            int k0 = c * 16;
            unsigned a[4][4];
#pragma unroll
            for (int mt = 0; mt < 4; ++mt)
                ldsm4(a[mt][0], a[mt][1], a[mt][2], a[mt][3],
                      A_s + (mt * 16 + lrow) * 776 + k0 + lcol);
#pragma unroll
            for (int nt = 0; nt < 3; ++nt) {
                uint2 bv = Wfu[(c * 6 + ng * 3 + nt) * 32 + lane];
#pragma unroll
                for (int mt = 0; mt < 4; ++mt)
                    mma16(acc[mt][nt], a[mt][0], a[mt][1], a[mt][2], a[mt][3], bv.x, bv.y);
            }
        }
        if (kp == 1) cp_wait<0>();   // make z_s staging visible before reduction
        __syncthreads();

        // --- reduce k-halves into z_s (holds xp) ---
        if (kp == 0) {
#pragma unroll
            for (int mt = 0; mt < 4; ++mt)
#pragma unroll
                for (int nt = 0; nt < 3; ++nt) {
                    int row = mt * 16 + gq;
                    int col = ng * 24 + nt * 8 + 2 * tig;
                    float2* z0 = (float2*)(z_s + row * 52 + col);
                    float2* z1 = (float2*)(z_s + (row + 8) * 52 + col);
                    float2 a = *z0;
                    a.x += acc[mt][nt][0]; a.y += acc[mt][nt][1];
                    *z0 = a;
                    float2 b2 = *z1;
                    b2.x += acc[mt][nt][2]; b2.y += acc[mt][nt][3];
                    *z1 = b2;
                }
        }
        __syncthreads();
        if (kp == 1) {
#pragma unroll
            for (int mt = 0; mt < 4; ++mt)
#pragma unroll
                for (int nt = 0; nt < 3; ++nt) {
                    int row = mt * 16 + gq;
                    int col = ng * 24 + nt * 8 + 2 * tig;
                    float2* z0 = (float2*)(z_s + row * 52 + col);
                    float2* z1 = (float2*)(z_s + (row + 8) * 52 + col);
                    float2 a = *z0;
                    a.x += acc[mt][nt][0]; a.y += acc[mt][nt][1];
                    *z0 = a;
                    float2 b2 = *z1;
                    b2.x += acc[mt][nt][2]; b2.y += acc[mt][nt][3];
                    *z1 = b2;
                }
        }
        __syncthreads();

        // --- pointwise gates + state update ---
        int nb = (t + 1) & 1;
#pragma unroll
        for (int j = 0; j < 6; ++j) {
            int idx = j * 128 + tid;
            int b = idx / 12, uu = idx % 12;
            const float* zr = z_s + b * 52;
            float f = sigm(zr[uu]);
            float i = sigm(zr[12 + uu]);
            float g = tanh2(zr[24 + uu]);
            float o = sigm(zr[36 + uu]);
            float c = f * cc[j] + i * g;
            cc[j] = c;
            float h = o * tanh2(c);
            g_h16[((size_t)(nb * 2 + d) * 64 + b) * 768 + us * 12 + uu] =
                __float2half_rn(h);
            if (t == 1023) {
                int unit = us * 12 + uu;
                g_hc[((size_t)(d * 2 + 0) * 64 + b) * 768 + unit] = h;
                g_hc[((size_t)(d * 2 + 1) * 64 + b) * 768 + unit] = c;
            }
        }
        gsync((unsigned)(t + 2));
    }
}

// ================= Phase C: out = [hf|hb] @ Why^T + by =================
__global__ __launch_bounds__(256) void outproj_kernel(
    const float* __restrict__ Why, const float* __restrict__ by,
    float* __restrict__ out)
{
    int w = blockIdx.x * 8 + (threadIdx.x >> 5);
    int lane = threadIdx.x & 31;
    int b = w >> 9, o = w & 511;
    const float* hf = g_hc + (size_t)b * 768;
    const float* hb = g_hc + 98304 + (size_t)b * 768;
    const float* wr = Why + (size_t)o * 1536;
    float s = 0.f;
    for (int k = lane; k < 768; k += 32) s += hf[k] * wr[k];
    for (int k = lane; k < 768; k += 32) s += hb[k] * wr[768 + k];
#pragma unroll
    for (int off = 16; off; off >>= 1) s += __shfl_xor_sync(0xffffffffu, s, off);
    if (lane == 0) out[(size_t)b * 512 + o] = s + by[o];
}

// ================= launch =================
extern "C" void kernel_launch(void* const* d_in, const int* in_sizes, int n_in,
                              void* d_out, int out_size) {
    const float* X   = (const float*)d_in[0];
    const float* Wxf = (const float*)d_in[1];
    const float* Whf = (const float*)d_in[2];
    const float* bf  = (const float*)d_in[3];
    const float* Wxb = (const float*)d_in[4];
    const float* Whb = (const float*)d_in[5];
    const float* bb  = (const float*)d_in[6];
    const float* Why = (const float*)d_in[7];
    const float* by  = (const float*)d_in[8];
    float* out = (float*)d_out;

    cudaFuncSetAttribute(xproj_kernel, cudaFuncAttributeMaxDynamicSharedMemorySize, 30720);
    cudaFuncSetAttribute(recur_kernel, cudaFuncAttributeMaxDynamicSharedMemorySize, 186368);

    __half2* x16;
    __half2* wx16;
    cudaGetSymbolAddress((void**)&x16, g_x16);
    cudaGetSymbolAddress((void**)&wx16, g_wx16);

    init_kernel<<<1, 1>>>();
    conv_kernel<<<8192, 1024>>>((const float4*)X, x16, 8388608);
    conv_kernel<<<384, 1024>>>((const float4*)Wxf, wx16, 393216);
    conv_kernel<<<384, 1024>>>((const float4*)Wxb, wx16 + 786432, 393216);
    xproj_kernel<<<dim3(96, 512), 256, 30720>>>(bf, bb);
    recur_kernel<<<NCTA, 128, 186368>>>(Whf, Whb);
    outproj_kernel<<<4096, 256>>>(Why, by, out);

    if (out_size >= 229376) {
        void* hc = nullptr;
        cudaGetSymbolAddress(&hc, g_hc);
        cudaMemcpyAsync(out + 32768, hc, 4 * 64 * 768 * sizeof(float),
                        cudaMemcpyDeviceToDevice, 0);
    }
}

// round 8
// speedup vs baseline: 1.4528x; 1.0587x over previous
#include <cuda_runtime.h>
#include <cuda_fp16.h>
#include <cstdint>

#define HID 768
#define TSEQ 1024
#define BATCH 64
#define NCTA 128

// ---------------- device scratch ----------------
__device__ float g_xp[402653184];            // [d][t][b][3072] fp32 (1.61 GB)
__device__ __half g_x16[64 * 1024 * 512];
__device__ __half g_wx16[6144 * 512];
__device__ __half g_h16[2 * 2 * BATCH * HID];   // h double buffer fp16
__device__ float g_hc[4 * BATCH * HID];         // hf, cf, hb, cb fp32
__device__ unsigned g_cnt2[2];
__device__ unsigned g_gen2[2];

__global__ void init_kernel() {
    g_cnt2[0] = 0; g_cnt2[1] = 0;
    g_gen2[0] = 0; g_gen2[1] = 0;
}

// ---------------- generic helpers ----------------
__device__ __forceinline__ unsigned h2u(__half2 h) {
    return *reinterpret_cast<unsigned*>(&h);
}
__device__ __forceinline__ void cp16(void* sdst, const void* gsrc) {
    unsigned sa = (unsigned)__cvta_generic_to_shared(sdst);
    asm volatile("cp.async.cg.shared.global [%0], [%1], 16;" :: "r"(sa), "l"(gsrc));
}
__device__ __forceinline__ void cp_commit() { asm volatile("cp.async.commit_group;"); }
template <int N> __device__ __forceinline__ void cp_wait() {
    asm volatile("cp.async.wait_group %0;" :: "n"(N));
}
__device__ __forceinline__ void ldsm4(unsigned& r0, unsigned& r1, unsigned& r2,
                                      unsigned& r3, const void* p) {
    unsigned a = (unsigned)__cvta_generic_to_shared(p);
    asm volatile("ldmatrix.sync.aligned.m8n8.x4.shared.b16 {%0,%1,%2,%3}, [%4];"
                 : "=r"(r0), "=r"(r1), "=r"(r2), "=r"(r3) : "r"(a));
}
__device__ __forceinline__ void mma16(float* acc, unsigned a0, unsigned a1,
                                      unsigned a2, unsigned a3, unsigned b0, unsigned b1) {
    asm volatile(
        "mma.sync.aligned.m16n8k16.row.col.f32.f16.f16.f32 "
        "{%0,%1,%2,%3},{%4,%5,%6,%7},{%8,%9},{%0,%1,%2,%3};"
        : "+f"(acc[0]), "+f"(acc[1]), "+f"(acc[2]), "+f"(acc[3])
        : "r"(a0), "r"(a1), "r"(a2), "r"(a3), "r"(b0), "r"(b1));
}
__device__ __forceinline__ float tanhapx(float x) {
    float y;
    asm("tanh.approx.f32 %0, %1;" : "=f"(y) : "f"(x));
    return y;
}
__device__ __forceinline__ float sigmapx(float x) {
    return 0.5f + 0.5f * tanhapx(0.5f * x);
}
// per-direction grid barrier (64 CTAs each)
__device__ __forceinline__ void gsyncd(int d, unsigned target) {
    __threadfence();
    __syncthreads();
    if (threadIdx.x == 0) {
        unsigned a = atomicAdd(&g_cnt2[d], 1u);
        if (a == 63u) {
            g_cnt2[d] = 0;
            __threadfence();
            atomicAdd(&g_gen2[d], 1u);
        } else {
            unsigned v;
            do {
                asm volatile("ld.acquire.gpu.u32 %0, [%1];" : "=r"(v) : "l"(&g_gen2[d]));
            } while (v < target);
        }
    }
    __syncthreads();
}

// ---------------- fp32 -> fp16 conversion ----------------
__global__ void conv_kernel(const float4* __restrict__ s, __half2* __restrict__ d, int n4) {
    int i = blockIdx.x * blockDim.x + threadIdx.x;
    if (i < n4) {
        float4 v = s[i];
        d[2 * i + 0] = __floats2half2_rn(v.x, v.y);
        d[2 * i + 1] = __floats2half2_rn(v.z, v.w);
    }
}

// ================= Phase A: xp = x @ [Wxf;Wxb]^T + bias (fp16 mma.sync) ===========
__global__ __launch_bounds__(256, 2) void xproj_kernel(
    const float* __restrict__ bf, const float* __restrict__ bb)
{
    extern __shared__ __half sm16[];
    __half* As = sm16;
    __half* Bs = sm16 + 2 * 128 * 40;
    const int tid = threadIdx.x;
    const int bn = blockIdx.x, bm = blockIdx.y;
    const int warp = tid >> 5, lane = tid & 31;
    const int wm = warp >> 1, wn = warp & 1;
    const int gq = lane >> 2, tig = lane & 3;
    const int lrow = lane & 15, lcol = (lane >> 4) << 3;

    auto stage = [&](int buf, int k0) {
        __half* Ad = As + buf * (128 * 40);
        __half* Bd = Bs + buf * (64 * 40);
#pragma unroll
        for (int j = 0; j < 2; ++j) {
            int idx = j * 256 + tid;
            int r = idx >> 2, q = idx & 3;
            cp16(Ad + r * 40 + q * 8, g_x16 + (size_t)(bm * 128 + r) * 512 + k0 + q * 8);
        }
        {
            int r = tid >> 2, q = tid & 3;
            cp16(Bd + r * 40 + q * 8, g_wx16 + (size_t)(bn * 64 + r) * 512 + k0 + q * 8);
        }
        cp_commit();
    };

    float acc[2][4][4];
#pragma unroll
    for (int a = 0; a < 2; ++a)
#pragma unroll
        for (int b = 0; b < 4; ++b)
#pragma unroll
            for (int c = 0; c < 4; ++c) acc[a][b][c] = 0.f;

    stage(0, 0);
#pragma unroll 1
    for (int it = 0; it < 16; ++it) {
        if (it < 15) { stage((it + 1) & 1, (it + 1) * 32); cp_wait<1>(); }
        else { cp_wait<0>(); }
        __syncthreads();
        const __half* Ab = As + (it & 1) * (128 * 40);
        const __half* Bb = Bs + (it & 1) * (64 * 40);
#pragma unroll
        for (int k16 = 0; k16 < 2; ++k16) {
            int k0 = k16 * 16;
            unsigned a[2][4];
#pragma unroll
            for (int mt = 0; mt < 2; ++mt)
                ldsm4(a[mt][0], a[mt][1], a[mt][2], a[mt][3],
                      Ab + (wm * 32 + mt * 16 + lrow) * 40 + k0 + lcol);
#pragma unroll
            for (int np = 0; np < 2; ++np) {
                unsigned r0, r1, r2, r3;
                ldsm4(r0, r1, r2, r3,
                      Bb + (wn * 32 + np * 16 + lrow) * 40 + k0 + lcol);
                mma16(acc[0][np * 2 + 0], a[0][0], a[0][1], a[0][2], a[0][3], r0, r2);
                mma16(acc[0][np * 2 + 1], a[0][0], a[0][1], a[0][2], a[0][3], r1, r3);
                mma16(acc[1][np * 2 + 0], a[1][0], a[1][1], a[1][2], a[1][3], r0, r2);
                mma16(acc[1][np * 2 + 1], a[1][0], a[1][1], a[1][2], a[1][3], r1, r3);
            }
        }
        __syncthreads();
    }
#pragma unroll
    for (int mt = 0; mt < 2; ++mt) {
#pragma unroll
        for (int r = 0; r < 2; ++r) {
            int m = bm * 128 + wm * 32 + mt * 16 + gq + r * 8;
            int b = m >> 10;
            int tx = m & 1023;
#pragma unroll
            for (int nt = 0; nt < 4; ++nt) {
                int n0 = bn * 64 + wn * 32 + nt * 8 + tig * 2;
                int d = (n0 >= 3072) ? 1 : 0;
                int g = n0 - d * 3072;
                int t = d ? (1023 - tx) : tx;
                float2 v;
                v.x = acc[mt][nt][r * 2 + 0] + (d ? bb[g] : bf[g]);
                v.y = acc[mt][nt][r * 2 + 1] + (d ? bb[g + 1] : bf[g + 1]);
                size_t addr = ((size_t)(d * 1024 + t) * 64 + b) * 3072 + g;
                *(float2*)(g_xp + addr) = v;
            }
        }
    }
}

// ================= Phase B: persistent recurrence, fp16 mma.sync, 256 thr =========
// 128 CTAs x 256 thr. CTA: d = cid>>6, us = cid&63 -> units [us*12, us*12+12) (48 gate rows).
// Warp w: kp = w&1 (K-half of 384), ng = (w>>1)&1 (24 gate cols), mw = w>>2 (32 batch rows).
// smem: Wf 48x6x32 uint2 fragments (73.7KB), A_s 64x776 half (99.3KB), z_s 64x52 f32 (13.3KB).
__global__ __launch_bounds__(256, 1) void recur_kernel(
    const float* __restrict__ Whf, const float* __restrict__ Whb)
{
    extern __shared__ char smraw[];
    __half2* Wf2 = (__half2*)smraw;                        // 9216 uint2 = 73728 B
    __half* A_s  = (__half*)(smraw + 73728);               // 64 x 776
    float*  z_s  = (float*)(smraw + 73728 + 99328);        // 64 x 52

    const int tid = threadIdx.x;
    const int warp = tid >> 5, lane = tid & 31;
    const int gq = lane >> 2, tig = lane & 3;
    const int lrow = lane & 15, lcol = (lane >> 4) << 3;
    const int kp = warp & 1;
    const int ng = (warp >> 1) & 1;
    const int mw = warp >> 2;
    const int gi = (warp >> 1) * 32 + lane;   // 0..127 within kp group
    const int cid = blockIdx.x;
    const int d = cid >> 6, us = cid & 63;
    const float* Wh = d ? Whb : Whf;

    // --- pre-arrange resident weight fragments (once) ---
    for (int idx = tid; idx < 9216; idx += 256) {
        int c = idx / 192;            // k16 chunk 0..47
        int r = idx % 192;
        int nt = r >> 5;              // 0..5
        int ln = r & 31;
        int fq = ln >> 2, ft = ln & 3;
        int gr = nt * 8 + fq;         // gate row 0..47
        int gb = gr / 12, uu = gr % 12;
        const float* w = Wh + (size_t)(gb * 768 + us * 12 + uu) * 768 + c * 16 + ft * 2;
        Wf2[idx * 2 + 0] = __floats2half2_rn(w[0], w[1]);
        Wf2[idx * 2 + 1] = __floats2half2_rn(w[8], w[9]);
    }
    // zero h buf0 for my slice
    for (int v = tid; v < 768; v += 256) {
        int b = v / 12, uu = v % 12;
        g_h16[((size_t)(0 * 2 + d) * 64 + b) * 768 + us * 12 + uu] = __float2half(0.f);
    }
    float cc[3];
#pragma unroll
    for (int j = 0; j < 3; ++j) cc[j] = 0.f;

    gsyncd(d, 1);

#pragma unroll 1
    for (int t = 0; t < 1024; ++t) {
        const __half* hcur = g_h16 + (size_t)((t & 1) * 2 + d) * BATCH * HID;
        const float* xpt = g_xp + (size_t)(d * 1024 + t) * BATCH * 3072;

        // --- stage: kp group stages its own contiguous k-half of h; kp1 also xp -> z_s ---
        {
            int base = kp * 384;
#pragma unroll 4
            for (int j = 0; j < 24; ++j) {
                int idx = j * 128 + gi;
                int b = idx / 48, q = idx % 48;
                cp16(A_s + b * 776 + base + q * 8, hcur + (size_t)b * 768 + base + q * 8);
            }
            cp_commit();
        }
        if (kp == 0) {
            cp_wait<0>();
            asm volatile("bar.sync 1, 128;");
        } else {
#pragma unroll
            for (int j = 0; j < 6; ++j) {
                int idx = j * 128 + gi;
                int b = idx / 12, seg = idx % 12;
                int gate = seg / 3, q = seg % 3;
                cp16(z_s + b * 52 + gate * 12 + q * 4,
                     xpt + (size_t)b * 3072 + gate * 768 + us * 12 + q * 4);
            }
            cp_commit();
            cp_wait<1>();
            asm volatile("bar.sync 2, 128;");
        }

        // --- mainloop: 24 contiguous k16 chunks for this warp's k-half ---
        float acc[2][3][4];
#pragma unroll
        for (int a = 0; a < 2; ++a)
#pragma unroll
            for (int b = 0; b < 3; ++b)
#pragma unroll
                for (int c = 0; c < 4; ++c) acc[a][b][c] = 0.f;

        const uint2* Wfu = (const uint2*)Wf2;
#pragma unroll 2
        for (int cnk = 0; cnk < 24; ++cnk) {
            int c = kp * 24 + cnk;
            int k0 = c * 16;
            unsigned a[2][4];
#pragma unroll
            for (int mt = 0; mt < 2; ++mt)
                ldsm4(a[mt][0], a[mt][1], a[mt][2], a[mt][3],
                      A_s + (mw * 32 + mt * 16 + lrow) * 776 + k0 + lcol);
#pragma unroll
            for (int nt = 0; nt < 3; ++nt) {
                uint2 bv = Wfu[(c * 6 + ng * 3 + nt) * 32 + lane];
#pragma unroll
                for (int mt = 0; mt < 2; ++mt)
                    mma16(acc[mt][nt], a[mt][0], a[mt][1], a[mt][2], a[mt][3], bv.x, bv.y);
            }
        }
        if (kp == 1) cp_wait<0>();   // z_s (xp) staged
        __syncthreads();

        // --- reduce k-halves into z_s (holds xp) ---
        if (kp == 0) {
#pragma unroll
            for (int mt = 0; mt < 2; ++mt)
#pragma unroll
                for (int nt = 0; nt < 3; ++nt) {
                    int row = mw * 32 + mt * 16 + gq;
                    int col = ng * 24 + nt * 8 + 2 * tig;
                    float2* z0 = (float2*)(z_s + row * 52 + col);
                    float2* z1 = (float2*)(z_s + (row + 8) * 52 + col);
                    float2 a = *z0;
                    a.x += acc[mt][nt][0]; a.y += acc[mt][nt][1];
                    *z0 = a;
                    float2 b2 = *z1;
                    b2.x += acc[mt][nt][2]; b2.y += acc[mt][nt][3];
                    *z1 = b2;
                }
        }
        __syncthreads();
        if (kp == 1) {
#pragma unroll
            for (int mt = 0; mt < 2; ++mt)
#pragma unroll
                for (int nt = 0; nt < 3; ++nt) {
                    int row = mw * 32 + mt * 16 + gq;
                    int col = ng * 24 + nt * 8 + 2 * tig;
                    float2* z0 = (float2*)(z_s + row * 52 + col);
                    float2* z1 = (float2*)(z_s + (row + 8) * 52 + col);
                    float2 a = *z0;
                    a.x += acc[mt][nt][0]; a.y += acc[mt][nt][1];
                    *z0 = a;
                    float2 b2 = *z1;
                    b2.x += acc[mt][nt][2]; b2.y += acc[mt][nt][3];
                    *z1 = b2;
                }
        }
        __syncthreads();

        // --- pointwise: 3 (b,unit) pairs per thread ---
        int nb = (t + 1) & 1;
        __half* hdst = g_h16 + (size_t)(nb * 2 + d) * BATCH * HID;
#pragma unroll
        for (int j = 0; j < 3; ++j) {
            int idx = j * 256 + tid;
            int b = idx / 12, uu = idx % 12;
            const float* zr = z_s + b * 52;
            float f = sigmapx(zr[uu]);
            float i = sigmapx(zr[12 + uu]);
            float g = tanhapx(zr[24 + uu]);
            float o = sigmapx(zr[36 + uu]);
            float c = f * cc[j] + i * g;
            cc[j] = c;
            float h = o * tanhapx(c);
            hdst[(size_t)b * 768 + us * 12 + uu] = __float2half_rn(h);
            if (t == 1023) {
                int unit = us * 12 + uu;
                g_hc[((size_t)(d * 2 + 0) * 64 + b) * 768 + unit] = h;
                g_hc[((size_t)(d * 2 + 1) * 64 + b) * 768 + unit] = c;
            }
        }
        gsyncd(d, (unsigned)(t + 2));
    }
}

// ================= Phase C: out = [hf|hb] @ Why^T + by =================
__global__ __launch_bounds__(256) void outproj_kernel(
    const float* __restrict__ Why, const float* __restrict__ by,
    float* __restrict__ out)
{
    int w = blockIdx.x * 8 + (threadIdx.x >> 5);
    int lane = threadIdx.x & 31;
    int b = w >> 9, o = w & 511;
    const float* hf = g_hc + (size_t)b * 768;
    const float* hb = g_hc + 98304 + (size_t)b * 768;
    const float* wr = Why + (size_t)o * 1536;
    float s = 0.f;
    for (int k = lane; k < 768; k += 32) s += hf[k] * wr[k];
    for (int k = lane; k < 768; k += 32) s += hb[k] * wr[768 + k];
#pragma unroll
    for (int off = 16; off; off >>= 1) s += __shfl_xor_sync(0xffffffffu, s, off);
    if (lane == 0) out[(size_t)b * 512 + o] = s + by[o];
}

// ================= launch =================
extern "C" void kernel_launch(void* const* d_in, const int* in_sizes, int n_in,
                              void* d_out, int out_size) {
    const float* X   = (const float*)d_in[0];
    const float* Wxf = (const float*)d_in[1];
    const float* Whf = (const float*)d_in[2];
    const float* bf  = (const float*)d_in[3];
    const float* Wxb = (const float*)d_in[4];
    const float* Whb = (const float*)d_in[5];
    const float* bb  = (const float*)d_in[6];
    const float* Why = (const float*)d_in[7];
    const float* by  = (const float*)d_in[8];
    float* out = (float*)d_out;

    cudaFuncSetAttribute(xproj_kernel, cudaFuncAttributeMaxDynamicSharedMemorySize, 30720);
    cudaFuncSetAttribute(recur_kernel, cudaFuncAttributeMaxDynamicSharedMemorySize, 186368);

    __half2* x16;
    __half2* wx16;
    cudaGetSymbolAddress((void**)&x16, g_x16);
    cudaGetSymbolAddress((void**)&wx16, g_wx16);

    init_kernel<<<1, 1>>>();
    conv_kernel<<<8192, 1024>>>((const float4*)X, x16, 8388608);
    conv_kernel<<<384, 1024>>>((const float4*)Wxf, wx16, 393216);
    conv_kernel<<<384, 1024>>>((const float4*)Wxb, wx16 + 786432, 393216);
    xproj_kernel<<<dim3(96, 512), 256, 30720>>>(bf, bb);
    recur_kernel<<<NCTA, 256, 186368>>>(Whf, Whb);
    outproj_kernel<<<4096, 256>>>(Why, by, out);

    if (out_size >= 229376) {
        void* hc = nullptr;
        cudaGetSymbolAddress(&hc, g_hc);
        cudaMemcpyAsync(out + 32768, hc, 4 * 64 * 768 * sizeof(float),
                        cudaMemcpyDeviceToDevice, 0);
    }
}